// round 1
// baseline (speedup 1.0000x reference)
#include <cuda_runtime.h>
#include <float.h>

#define Bn 4
#define Nn 16384
#define Sn 4096
#define Cin 256
#define Cout 256

// Scratch (device globals -- allocation-free per harness rules)
__device__ float g_G[Bn * Sn * Cout];   // [b][s][o]  (W @ points2 + bias), 16.8 MB
__device__ float g_w[Bn * Nn * 3];      // interp weights
__device__ int   g_i[Bn * Nn * 3];      // neighbor indices

// ---------------------------------------------------------------------------
// K1: G[b][s][o] = sum_c P[b][c][s] * W[o][c] + bias[o]
// Tiles: 64 s x 64 o, K-step 16, 256 threads, 4x4 per-thread register tile.
// ---------------------------------------------------------------------------
__global__ void k1_gemm(const float* __restrict__ P,
                        const float* __restrict__ W,
                        const float* __restrict__ bias) {
    __shared__ float sP[16][64];   // [k][s]
    __shared__ float sW[16][64];   // [k][o]

    const int b  = blockIdx.z;
    const int s0 = blockIdx.x * 64;
    const int o0 = blockIdx.y * 64;
    const int tid = threadIdx.x;
    const int tx = tid & 15;        // s-quad
    const int ty = tid >> 4;        // o-quad

    float acc[4][4];
#pragma unroll
    for (int j = 0; j < 4; j++)
#pragma unroll
        for (int i = 0; i < 4; i++) acc[j][i] = 0.f;

    const float* Pb = P + b * Cin * Sn;

    for (int k0 = 0; k0 < Cin; k0 += 16) {
        // load P tile: (k, s)
        {
            const int lk = tid >> 6;     // 0..3
            const int ls = tid & 63;
#pragma unroll
            for (int i = 0; i < 4; i++)
                sP[lk + 4 * i][ls] = Pb[(k0 + lk + 4 * i) * Sn + s0 + ls];
        }
        // load W tile: (k, o), W is [o][c] contiguous in c
        {
            const int wk = tid & 15;
            const int wo = tid >> 4;     // 0..15
#pragma unroll
            for (int i = 0; i < 4; i++)
                sW[wk][wo + 16 * i] = W[(o0 + wo + 16 * i) * Cin + k0 + wk];
        }
        __syncthreads();

#pragma unroll
        for (int k = 0; k < 16; k++) {
            const float4 a  = *(const float4*)&sP[k][tx * 4];
            const float4 w4 = *(const float4*)&sW[k][ty * 4];
            const float av[4] = {a.x, a.y, a.z, a.w};
            const float wv[4] = {w4.x, w4.y, w4.z, w4.w};
#pragma unroll
            for (int j = 0; j < 4; j++)
#pragma unroll
                for (int i = 0; i < 4; i++)
                    acc[j][i] = fmaf(av[i], wv[j], acc[j][i]);
        }
        __syncthreads();
    }

    // epilogue: fold bias, write G[b][s][o] (float4 along o)
    float* Gb = g_G + b * Sn * Cout;
    const float bb0 = bias[o0 + ty * 4 + 0];
    const float bb1 = bias[o0 + ty * 4 + 1];
    const float bb2 = bias[o0 + ty * 4 + 2];
    const float bb3 = bias[o0 + ty * 4 + 3];
#pragma unroll
    for (int i = 0; i < 4; i++) {
        float4 v;
        v.x = acc[0][i] + bb0;
        v.y = acc[1][i] + bb1;
        v.z = acc[2][i] + bb2;
        v.w = acc[3][i] + bb3;
        *(float4*)&Gb[(s0 + tx * 4 + i) * Cout + o0 + ty * 4] = v;
    }
}

// ---------------------------------------------------------------------------
// K2: 3-NN search. One thread per query point; xyz2 staged in smem as
// (-2x, -2y, -2z, |p|^2) so distance-rank value is 3 FMAs.
// ---------------------------------------------------------------------------
__global__ void k2_knn(const float* __restrict__ xyz1,
                       const float* __restrict__ xyz2) {
    extern __shared__ unsigned char smem_raw[];
    float4* qtab = (float4*)smem_raw;   // [Sn] = 64 KB

    const int b   = blockIdx.y;
    const int n0  = blockIdx.x * 256;
    const int tid = threadIdx.x;

    const float* x2 = xyz2 + b * 3 * Sn;
    for (int s = tid; s < Sn; s += 256) {
        const float x = x2[s];
        const float y = x2[Sn + s];
        const float z = x2[2 * Sn + s];
        qtab[s] = make_float4(-2.f * x, -2.f * y, -2.f * z, x * x + y * y + z * z);
    }
    __syncthreads();

    const int n = n0 + tid;
    const float* x1 = xyz1 + b * 3 * Nn;
    const float px = x1[n];
    const float py = x1[Nn + n];
    const float pz = x1[2 * Nn + n];

    float d0 = FLT_MAX, d1 = FLT_MAX, d2 = FLT_MAX;
    int   i0 = 0, i1 = 0, i2 = 0;

#pragma unroll 4
    for (int s = 0; s < Sn; s++) {
        const float4 q = qtab[s];
        const float e = fmaf(px, q.x, fmaf(py, q.y, fmaf(pz, q.z, q.w)));
        if (e < d2) {
            if (e < d0)      { d2 = d1; i2 = i1; d1 = d0; i1 = i0; d0 = e; i0 = s; }
            else if (e < d1) { d2 = d1; i2 = i1; d1 = e;  i1 = s; }
            else             { d2 = e;  i2 = s; }
        }
    }

    // full squared distances need + |p1|^2
    const float pn = px * px + py * py + pz * pz;
    const float r0 = 1.f / (d0 + pn + 1e-8f);
    const float r1 = 1.f / (d1 + pn + 1e-8f);
    const float r2 = 1.f / (d2 + pn + 1e-8f);
    const float inv = 1.f / (r0 + r1 + r2);

    const int base = (b * Nn + n) * 3;
    g_w[base + 0] = r0 * inv;
    g_w[base + 1] = r1 * inv;
    g_w[base + 2] = r2 * inv;
    g_i[base + 0] = i0;
    g_i[base + 1] = i1;
    g_i[base + 2] = i2;
}

// ---------------------------------------------------------------------------
// K3: gather + weighted sum + transpose-write.
// CTA = (b, tile of 64 points), 256 threads (one per output channel).
// Stage [p][ch] in padded smem, then coalesced n-contiguous writes.
// ---------------------------------------------------------------------------
#define ACC_PITCH 261   // 256 + 5: conflict-free gather-writes, ~2-way reads

__global__ void k3_gather(float* __restrict__ out) {
    extern __shared__ unsigned char smem_raw[];
    float* acc = (float*)smem_raw;            // [64][ACC_PITCH]
    __shared__ float sw[64 * 3];
    __shared__ int   si[64 * 3];

    const int b   = blockIdx.y;
    const int n0  = blockIdx.x * 64;
    const int tid = threadIdx.x;

    for (int t = tid; t < 64 * 3; t += 256) {
        sw[t] = g_w[(b * Nn + n0) * 3 + t];
        si[t] = g_i[(b * Nn + n0) * 3 + t];
    }
    __syncthreads();

    const float* Gb = g_G + b * Sn * Cout;
    const int o = tid;   // 0..255

#pragma unroll 4
    for (int p = 0; p < 64; p++) {
        const float w0 = sw[3 * p + 0];
        const float w1 = sw[3 * p + 1];
        const float w2 = sw[3 * p + 2];
        const int   j0 = si[3 * p + 0];
        const int   j1 = si[3 * p + 1];
        const int   j2 = si[3 * p + 2];
        float v = w0 * Gb[j0 * Cout + o];
        v = fmaf(w1, Gb[j1 * Cout + o], v);
        v = fmaf(w2, Gb[j2 * Cout + o], v);
        acc[p * ACC_PITCH + o] = v;
    }
    __syncthreads();

    // write out[b][c][n0 + 0..63], coalesced float4 along n
    float* ob = out + b * Cout * Nn;
    for (int idx = tid; idx < 256 * 16; idx += 256) {
        const int c = idx >> 4;
        const int g = idx & 15;
        float4 v;
        v.x = acc[(4 * g + 0) * ACC_PITCH + c];
        v.y = acc[(4 * g + 1) * ACC_PITCH + c];
        v.z = acc[(4 * g + 2) * ACC_PITCH + c];
        v.w = acc[(4 * g + 3) * ACC_PITCH + c];
        *(float4*)&ob[c * Nn + n0 + 4 * g] = v;
    }
}

// ---------------------------------------------------------------------------
extern "C" void kernel_launch(void* const* d_in, const int* in_sizes, int n_in,
                              void* d_out, int out_size) {
    const float* xyz1 = (const float*)d_in[0];   // [B,3,N]
    const float* xyz2 = (const float*)d_in[1];   // [B,3,S]
    const float* P    = (const float*)d_in[2];   // [B,Cin,S]
    const float* W    = (const float*)d_in[3];   // [Cout,Cin]
    const float* bias = (const float*)d_in[4];   // [Cout]
    float* out = (float*)d_out;                  // [B,Cout,N]

    cudaFuncSetAttribute(k2_knn, cudaFuncAttributeMaxDynamicSharedMemorySize,
                         Sn * (int)sizeof(float4));
    cudaFuncSetAttribute(k3_gather, cudaFuncAttributeMaxDynamicSharedMemorySize,
                         64 * ACC_PITCH * (int)sizeof(float));

    k1_gemm<<<dim3(Sn / 64, Cout / 64, Bn), 256>>>(P, W, bias);
    k2_knn<<<dim3(Nn / 256, Bn), 256, Sn * sizeof(float4)>>>(xyz1, xyz2);
    k3_gather<<<dim3(Nn / 64, Bn), 256, 64 * ACC_PITCH * sizeof(float)>>>(out);
}